// round 15
// baseline (speedup 1.0000x reference)
#include <cuda_runtime.h>
#include <cuda_fp16.h>
#include <math.h>
#include <stdint.h>

#define BB 16
#define SS 2048
#define DD 512

// ---------------------------------------------------------------------------
// Scratch (device globals — no allocation allowed)
// ---------------------------------------------------------------------------
__device__ float g_Wkp[DD * DD];     // E1 @ Wk
__device__ float g_Bqk[DD * DD];     // Wkp^T @ Wq
__device__ float g_Wvp[DD * DD];     // E2 @ Wv
__device__ float g_Wvo[DD * DD];     // Wo @ Wvp
__device__ float g_bqk[DD];          // Wkp^T @ bq
__device__ float g_bvp[DD];          // E2 @ bv
__device__ float g_bvo[DD];          // Wo @ bvp + bo
__device__ float g_zero512[DD];
__device__ float g_rowsum[(size_t)BB * SS];        // per-row exp sums

__device__ __half g_Bqk_h[DD * DD];
__device__ __half g_Wvo_h[DD * DD];
__device__ __half g_qp_h[(size_t)BB * SS * DD];
__device__ __half g_kin_h[(size_t)BB * SS * DD];
__device__ __half g_vpT_h[(size_t)BB * SS * DD];   // [b][n][t]
__device__ __half g_attn_h[(size_t)BB * SS * SS];  // fp16 exp copy (unnormalized)

// ---------------------------------------------------------------------------
// helpers
// ---------------------------------------------------------------------------
__device__ __forceinline__ uint32_t smem_u32(const void* p) {
    uint32_t a;
    asm("{ .reg .u64 t; cvta.to.shared.u64 t, %1; cvt.u32.u64 %0, t; }"
        : "=r"(a) : "l"(p));
    return a;
}
__device__ __forceinline__ void cp_async16(uint32_t dst, const void* src) {
    asm volatile("cp.async.cg.shared.global [%0], [%1], 16;"
                 :: "r"(dst), "l"(src) : "memory");
}
__device__ __forceinline__ void cp_commit() {
    asm volatile("cp.async.commit_group;" ::: "memory");
}
__device__ __forceinline__ void cp_wait1() {
    asm volatile("cp.async.wait_group 1;" ::: "memory");
}
__device__ __forceinline__ void cp_wait0() {
    asm volatile("cp.async.wait_group 0;" ::: "memory");
}
__device__ __forceinline__ void ldsm4(uint32_t r[4], uint32_t addr) {
    asm volatile("ldmatrix.sync.aligned.m8n8.x4.shared.b16 {%0,%1,%2,%3}, [%4];"
                 : "=r"(r[0]), "=r"(r[1]), "=r"(r[2]), "=r"(r[3]) : "r"(addr));
}
__device__ __forceinline__ void mma_f16(float c[4], const uint32_t a[4],
                                        uint32_t b0, uint32_t b1) {
    asm volatile(
        "mma.sync.aligned.m16n8k16.row.col.f32.f16.f16.f32 "
        "{%0,%1,%2,%3}, {%4,%5,%6,%7}, {%8,%9}, {%0,%1,%2,%3};"
        : "+f"(c[0]), "+f"(c[1]), "+f"(c[2]), "+f"(c[3])
        : "r"(a[0]), "r"(a[1]), "r"(a[2]), "r"(a[3]), "r"(b0), "r"(b1));
}

// SMEM tile: 128 rows x 128B. swizzle: 16B chunk ch -> ch ^ (row&7)
__device__ __forceinline__ uint32_t tile_off(int row, int ch) {
    return (uint32_t)(row * 128 + ((ch ^ (row & 7)) * 16));
}

__device__ __forceinline__ void make_off2(int lane, int m0, int n0,
                                          uint32_t apre[4], uint32_t ax[4], int& ac0,
                                          uint32_t bpre[2], uint32_t bx[2], int& bc0)
{
#pragma unroll
    for (int i = 0; i < 4; i++) {
        const int r = m0 + i * 16 + (lane & 7) + ((lane >> 3) & 1) * 8;
        apre[i] = (uint32_t)(r * 128);
        ax[i]   = (uint32_t)(r & 7);
    }
    ac0 = lane >> 4;
#pragma unroll
    for (int j = 0; j < 2; j++) {
        const int r = n0 + j * 16 + (lane & 7) + ((lane >> 4) & 1) * 8;
        bpre[j] = (uint32_t)(r * 128);
        bx[j]   = (uint32_t)(r & 7);
    }
    bc0 = (lane >> 3) & 1;
}

// 64-K chunk = 4 k16 steps, double-buffered fragments
__device__ __forceinline__ void compute_chunk_f16(
    uint32_t stA, uint32_t stB,
    const uint32_t apre[4], const uint32_t ax[4], int ac0,
    const uint32_t bpre[2], const uint32_t bx[2], int bc0,
    float c[4][4][4])
{
    uint32_t a[2][4][4], b[2][2][4];
#pragma unroll
    for (int i = 0; i < 4; i++)
        ldsm4(a[0][i], stA + apre[i] + ((((uint32_t)ac0) ^ ax[i]) << 4));
#pragma unroll
    for (int j = 0; j < 2; j++)
        ldsm4(b[0][j], stB + bpre[j] + ((((uint32_t)bc0) ^ bx[j]) << 4));
#pragma unroll
    for (int ks = 0; ks < 4; ks++) {
        const int cur = ks & 1, nxt = cur ^ 1;
        if (ks < 3) {
            const uint32_t chA = (uint32_t)((ks + 1) * 2 + ac0);
            const uint32_t chB = (uint32_t)((ks + 1) * 2 + bc0);
#pragma unroll
            for (int i = 0; i < 4; i++)
                ldsm4(a[nxt][i], stA + apre[i] + ((chA ^ ax[i]) << 4));
#pragma unroll
            for (int j = 0; j < 2; j++)
                ldsm4(b[nxt][j], stB + bpre[j] + ((chB ^ bx[j]) << 4));
        }
#pragma unroll
        for (int i = 0; i < 4; i++)
#pragma unroll
            for (int j = 0; j < 4; j++)
                mma_f16(c[i][j], a[cur][i],
                        b[cur][j >> 1][(j & 1) * 2], b[cur][j >> 1][(j & 1) * 2 + 1]);
    }
}

#define TG_THREADS 256
#define TG_STAGE   32768
#define TG_SMEM    (3 * TG_STAGE)

// ---------------------------------------------------------------------------
// fp16 GEMM with fused softmax plumbing.
//   rowsumW non-null  -> scores mode: write exp(alpha*s) fp32+fp16, atomic rowsums
//   rowsumR non-null  -> divide each output row by rowsum before +bias
//   normData non-null & blockIdx.x >= gemmX -> CTA normalizes attn in place
// ---------------------------------------------------------------------------
__global__ __launch_bounds__(TG_THREADS, 2)
void tgemm_f16_kernel(const __half* __restrict__ A, const __half* __restrict__ Bm,
                      float* outF, __half* outH, const float* __restrict__ bias,
                      float* rowsumW, const float* rowsumR, float* normData,
                      int gemmX,
                      int M, int N, int K, float alpha,
                      long long sA, long long sB, long long sC)
{
    extern __shared__ char smem[];
    const uint32_t sb = smem_u32(smem);
    const int tid  = threadIdx.x;
    const int lane = tid & 31;
    const int wid  = tid >> 5;
    const long long bz = blockIdx.z;

    // ---- heterogeneous normalize path (overlaps with GEMM CTAs) ----
    if (normData && blockIdx.x >= gemmX) {
        const int slice = blockIdx.x - gemmX;              // 0..3 (512 cols each)
        const int rowBase = blockIdx.y * 128;
        float* dataB = normData + bz * (long long)SS * SS;
        const float* rs = rowsumR + bz * SS;
        float* sinv = (float*)smem;
        if (tid < 128) sinv[tid] = 1.0f / rs[rowBase + tid];
        __syncthreads();
#pragma unroll 4
        for (int g = tid; g < 128 * 128; g += TG_THREADS) {  // 16384 float4s
            const int row = g >> 7;
            const int c4  = g & 127;
            const long long off = (long long)(rowBase + row) * SS + slice * 512 + c4 * 4;
            const float inv = sinv[row];
            float4 v = *(float4*)(dataB + off);
            v.x *= inv; v.y *= inv; v.z *= inv; v.w *= inv;
            *(float4*)(dataB + off) = v;
        }
        return;
    }

    const int m0 = (wid & 1) * 64;
    const int n0 = (wid >> 1) * 32;

    A  += bz * sA;
    Bm += bz * sB;
    if (outF) outF += bz * sC;
    if (outH) outH += bz * sC;
    if (rowsumW) rowsumW += bz * SS;
    const float* rsR = rowsumR ? rowsumR + bz * SS : nullptr;

    const int rowBase = blockIdx.y * 128;
    const int colBase = blockIdx.x * 128;

    int ldRow[4], ldCh[4];
    uint32_t ldOff[4];
#pragma unroll
    for (int i = 0; i < 4; i++) {
        const int u = tid + i * 256;
        ldRow[i] = u >> 3;
        ldCh[i]  = u & 7;
        ldOff[i] = tile_off(ldRow[i], ldCh[i]);
    }

    uint32_t apre[4], ax[4], bpre[2], bx[2];
    int ac0, bc0;
    make_off2(lane, m0, n0, apre, ax, ac0, bpre, bx, bc0);

    float c[4][4][4];
#pragma unroll
    for (int i = 0; i < 4; i++)
#pragma unroll
        for (int j = 0; j < 4; j++)
#pragma unroll
            for (int e = 0; e < 4; e++) c[i][j][e] = 0.0f;

    const int nc = K >> 6;

    auto load_stage = [&](int cidx) {
        const uint32_t dst = sb + (uint32_t)(cidx % 3) * TG_STAGE;
        const long long kb = (long long)cidx * 64;
#pragma unroll
        for (int i = 0; i < 4; i++) {
            const long long ea = (long long)(rowBase + ldRow[i]) * K + kb + ldCh[i] * 8;
            const long long eb = (long long)(colBase + ldRow[i]) * K + kb + ldCh[i] * 8;
            cp_async16(dst +          ldOff[i], A  + ea);
            cp_async16(dst + 16384u + ldOff[i], Bm + eb);
        }
        cp_commit();
    };

    load_stage(0);
    if (nc > 1) load_stage(1);

    for (int cidx = 0; cidx < nc; cidx++) {
        if (cidx + 1 < nc) cp_wait1(); else cp_wait0();
        __syncthreads();
        if (cidx + 2 < nc) load_stage(cidx + 2);
        const uint32_t st = sb + (uint32_t)(cidx % 3) * TG_STAGE;
        compute_chunk_f16(st, st + 16384u, apre, ax, ac0, bpre, bx, bc0, c);
    }
    __syncthreads();

    float* sf = (float*)smem;
#pragma unroll
    for (int i = 0; i < 4; i++) {
        const int r = m0 + i * 16 + (lane >> 2);
#pragma unroll
        for (int j = 0; j < 4; j++) {
            const int cc = n0 + j * 8 + (lane & 3) * 2;
            sf[r * 136 + cc]           = c[i][j][0];
            sf[r * 136 + cc + 1]       = c[i][j][1];
            sf[(r + 8) * 136 + cc]     = c[i][j][2];
            sf[(r + 8) * 136 + cc + 1] = c[i][j][3];
        }
    }
    __syncthreads();

    if (rowsumW) {
        // scores mode: e = exp(alpha*s); vectorized warp-per-row epilogue
#pragma unroll 2
        for (int it = 0; it < 16; it++) {
            const int r = it * 8 + wid;
            float4 sv = *(float4*)&sf[r * 136 + lane * 4];
            float e0 = __expf(sv.x * alpha);
            float e1 = __expf(sv.y * alpha);
            float e2 = __expf(sv.z * alpha);
            float e3 = __expf(sv.w * alpha);
            const long long go = (long long)(rowBase + r) * N + colBase + lane * 4;
            *(float4*)(outF + go) = make_float4(e0, e1, e2, e3);
            __half2 h0 = __floats2half2_rn(e0, e1);
            __half2 h1 = __floats2half2_rn(e2, e3);
            uint2 hp;
            hp.x = *reinterpret_cast<uint32_t*>(&h0);
            hp.y = *reinterpret_cast<uint32_t*>(&h1);
            *(uint2*)(outH + go) = hp;
            float t = (e0 + e1) + (e2 + e3);
#pragma unroll
            for (int o = 16; o > 0; o >>= 1) t += __shfl_xor_sync(0xffffffffu, t, o);
            if (lane == 0) atomicAdd(&rowsumW[rowBase + r], t);
        }
    } else {
#pragma unroll 4
        for (int e = tid; e < 128 * 128; e += TG_THREADS) {
            const int r = e >> 7, cc = e & 127;
            float v = sf[r * 136 + cc] * alpha;
            if (rsR) v /= rsR[rowBase + r];
            const int gc = colBase + cc;
            if (bias) v += bias[gc];
            const long long gi = (long long)(rowBase + r) * N + gc;
            if (outF) outF[gi] = v;
            if (outH) outH[gi] = __float2half_rn(v);
        }
    }
}

// ---------------------------------------------------------------------------
// Merged projection GEMM (z = 0: q' ; 1: vproj(trans)).
// ---------------------------------------------------------------------------
struct ProjArgs {
    const float*  A[2];
    const __half* Bh[2];
    __half*       out[2];
    const float*  bias[2];
    int           trans[2];
};

__global__ __launch_bounds__(TG_THREADS, 2)
void tgemm_proj_kernel(ProjArgs pa, int M, int N, int K)
{
    extern __shared__ char smem[];
    const uint32_t sb = smem_u32(smem);
    const int tid  = threadIdx.x;
    const int lane = tid & 31;
    const int wid  = tid >> 5;
    const int m0   = (wid & 1) * 64;
    const int n0   = (wid >> 1) * 32;
    const int z    = blockIdx.z;

    const float* A    = pa.A[z];
    const __half* Bh  = pa.Bh[z];
    __half* out       = pa.out[z];
    const float* bias = pa.bias[z];
    const int transOut = pa.trans[z];

    const int rowBase = blockIdx.y * 128;
    const int colBase = blockIdx.x * 128;

    int ldRow[4], ldCh[4];
    uint32_t ldOff[4];
#pragma unroll
    for (int i = 0; i < 4; i++) {
        const int u = tid + i * 256;
        ldRow[i] = u >> 3;
        ldCh[i]  = u & 7;
        ldOff[i] = tile_off(ldRow[i], ldCh[i]);
    }

    uint32_t apre[4], ax[4], bpre[2], bx[2];
    int ac0, bc0;
    make_off2(lane, m0, n0, apre, ax, ac0, bpre, bx, bc0);

    float c[4][4][4];
#pragma unroll
    for (int i = 0; i < 4; i++)
#pragma unroll
        for (int j = 0; j < 4; j++)
#pragma unroll
            for (int e = 0; e < 4; e++) c[i][j][e] = 0.0f;

    const int nc = K >> 6;

    auto issueB = [&](int cidx) {
        const uint32_t dst = sb + 16384u + (uint32_t)(cidx % 3) * TG_STAGE;
        const long long kb = (long long)cidx * 64;
#pragma unroll
        for (int i = 0; i < 4; i++) {
            const long long eb = (long long)(colBase + ldRow[i]) * K + kb + ldCh[i] * 8;
            cp_async16(dst + ldOff[i], Bh + eb);
        }
        cp_commit();
    };
    auto ldgA = [&](int cidx, float4 ar[4][2]) {
        const long long kb = (long long)cidx * 64;
#pragma unroll
        for (int i = 0; i < 4; i++) {
            const float* p = A + (long long)(rowBase + ldRow[i]) * K + kb + ldCh[i] * 8;
            ar[i][0] = *(const float4*)(p);
            ar[i][1] = *(const float4*)(p + 4);
        }
    };
    auto stsA = [&](int cidx, const float4 ar[4][2]) {
        char* base = smem + (cidx % 3) * TG_STAGE;
#pragma unroll
        for (int i = 0; i < 4; i++) {
            uint4 t;
            __half2 h0 = __floats2half2_rn(ar[i][0].x, ar[i][0].y);
            __half2 h1 = __floats2half2_rn(ar[i][0].z, ar[i][0].w);
            __half2 h2 = __floats2half2_rn(ar[i][1].x, ar[i][1].y);
            __half2 h3 = __floats2half2_rn(ar[i][1].z, ar[i][1].w);
            t.x = *reinterpret_cast<uint32_t*>(&h0);
            t.y = *reinterpret_cast<uint32_t*>(&h1);
            t.z = *reinterpret_cast<uint32_t*>(&h2);
            t.w = *reinterpret_cast<uint32_t*>(&h3);
            *(uint4*)(base + ldOff[i]) = t;
        }
    };

    float4 ar[4][2];
    ldgA(0, ar);
    issueB(0);
    if (nc > 1) issueB(1);
    stsA(0, ar);
    if (nc > 1) ldgA(1, ar);

    for (int cidx = 0; cidx < nc; cidx++) {
        if (cidx + 1 < nc) cp_wait1(); else cp_wait0();
        __syncthreads();
        if (cidx + 2 < nc) issueB(cidx + 2);
        if (cidx + 1 < nc) stsA(cidx + 1, ar);
        if (cidx + 2 < nc) ldgA(cidx + 2, ar);
        const uint32_t st = sb + (uint32_t)(cidx % 3) * TG_STAGE;
        compute_chunk_f16(st, st + 16384u, apre, ax, ac0, bpre, bx, bc0, c);
    }
    __syncthreads();

    float* sf = (float*)smem;
#pragma unroll
    for (int i = 0; i < 4; i++) {
        const int r = m0 + i * 16 + (lane >> 2);
#pragma unroll
        for (int j = 0; j < 4; j++) {
            const int cc = n0 + j * 8 + (lane & 3) * 2;
            sf[r * 136 + cc]           = c[i][j][0];
            sf[r * 136 + cc + 1]       = c[i][j][1];
            sf[(r + 8) * 136 + cc]     = c[i][j][2];
            sf[(r + 8) * 136 + cc + 1] = c[i][j][3];
        }
    }
    __syncthreads();
#pragma unroll 4
    for (int e = tid; e < 128 * 128; e += TG_THREADS) {
        int r, cc;
        if (transOut) { r = e & 127; cc = e >> 7; }
        else          { r = e >> 7;  cc = e & 127; }
        float v = sf[r * 136 + cc] + bias[colBase + cc];
        long long gi;
        if (transOut) {
            const int grow = rowBase + r;
            gi = (long long)(grow >> 11) * ((long long)DD * SS)
               + (long long)(colBase + cc) * SS + (grow & 2047);
        } else {
            gi = (long long)(rowBase + r) * N + colBase + cc;
        }
        out[gi] = __float2half_rn(v);
    }
}

// ---------------------------------------------------------------------------
// Fold GEMM (512^3, fp32): 64x64 tile, BK=16. grid (8,8,2). tn: C = A^T @ B.
// ---------------------------------------------------------------------------
struct FoldArgs {
    const float* A[2];
    const float* B[2];
    float*       C[2];
    int          tn[2];
};

__global__ __launch_bounds__(256)
void fold_gemm_kernel(FoldArgs fa)
{
    const int z = blockIdx.z;
    const float* A = fa.A[z];
    const float* B = fa.B[z];
    float* C = fa.C[z];
    const int tn = fa.tn[z];

    __shared__ float As[16][68];
    __shared__ float Bs[16][68];
    const int tid = threadIdx.x;
    const int tx = tid & 15, ty = tid >> 4;
    const int m0 = blockIdx.y * 64, n0 = blockIdx.x * 64;

    float acc[4][4];
#pragma unroll
    for (int i = 0; i < 4; i++)
#pragma unroll
        for (int j = 0; j < 4; j++) acc[i][j] = 0.0f;

    for (int k0 = 0; k0 < DD; k0 += 16) {
        if (tn) {
            const int kr = tid >> 4, mc = (tid & 15) * 4;
            float4 a = *(const float4*)(A + (long long)(k0 + kr) * DD + m0 + mc);
            *(float4*)&As[kr][mc] = a;
        } else {
            const int r = tid >> 2, kc = (tid & 3) * 4;
            float4 a = *(const float4*)(A + (long long)(m0 + r) * DD + k0 + kc);
            As[kc + 0][r] = a.x; As[kc + 1][r] = a.y;
            As[kc + 2][r] = a.z; As[kc + 3][r] = a.w;
        }
        {
            const int kr = tid >> 4, ncc = (tid & 15) * 4;
            float4 b = *(const float4*)(B + (long long)(k0 + kr) * DD + n0 + ncc);
            *(float4*)&Bs[kr][ncc] = b;
        }
        __syncthreads();
#pragma unroll
        for (int k = 0; k < 16; k++) {
            float4 a = *(const float4*)&As[k][ty * 4];
            float4 b = *(const float4*)&Bs[k][tx * 4];
            float av[4] = {a.x, a.y, a.z, a.w};
            float bv[4] = {b.x, b.y, b.z, b.w};
#pragma unroll
            for (int i = 0; i < 4; i++)
#pragma unroll
                for (int j = 0; j < 4; j++)
                    acc[i][j] = fmaf(av[i], bv[j], acc[i][j]);
        }
        __syncthreads();
    }
#pragma unroll
    for (int i = 0; i < 4; i++) {
        float4 v = {acc[i][0], acc[i][1], acc[i][2], acc[i][3]};
        *(float4*)(C + (long long)(m0 + ty * 4 + i) * DD + n0 + tx * 4) = v;
    }
}

// out[p] = sum_d E'[p,d]*b[d] + (add ? add[p] : 0); transE: E'[p,d] = E[d,p]
__global__ void fuse_bias_kernel(const float* __restrict__ E,
                                 const float* __restrict__ b,
                                 const float* __restrict__ add,
                                 float* __restrict__ out, int transE)
{
    __shared__ float red[8];
    const int p = blockIdx.x;
    float s = 0.0f;
    for (int d = threadIdx.x; d < DD; d += 256) {
        float e = transE ? E[(long long)d * DD + p] : E[(long long)p * DD + d];
        s = fmaf(e, b[d], s);
    }
#pragma unroll
    for (int off = 16; off > 0; off >>= 1) s += __shfl_xor_sync(0xffffffffu, s, off);
    if ((threadIdx.x & 31) == 0) red[threadIdx.x >> 5] = s;
    __syncthreads();
    if (threadIdx.x == 0) {
        float t = 0.0f;
#pragma unroll
        for (int i = 0; i < 8; i++) t += red[i];
        out[p] = t + (add ? add[p] : 0.0f);
    }
}

// convert 2 weight matrices fp32 -> fp16
__global__ void cvt2_kernel(const float* __restrict__ s0, __half* __restrict__ d0,
                            const float* __restrict__ s1, __half* __restrict__ d1)
{
    const float* x = blockIdx.z ? s1 : s0;
    __half* y      = blockIdx.z ? d1 : d0;
    const int n = DD * DD;
    for (int i = blockIdx.x * blockDim.x + threadIdx.x; i < n;
         i += gridDim.x * blockDim.x)
        y[i] = __float2half_rn(x[i]);
}

// big fp32 -> fp16 convert (k_in)
__global__ void cvt_big_kernel(const float* __restrict__ x, __half* __restrict__ y,
                               long long n)
{
    long long i = (long long)blockIdx.x * blockDim.x + threadIdx.x;
    const long long stride = (long long)gridDim.x * blockDim.x;
    for (; i < n; i += stride) {
        float2 v = *(const float2*)(x + i * 2);
        __half2 h = __floats2half2_rn(v.x, v.y);
        *(__half2*)(y + i * 2) = h;
    }
}

// ---------------------------------------------------------------------------
// Launch
// ---------------------------------------------------------------------------
extern "C" void kernel_launch(void* const* d_in, const int* in_sizes, int n_in,
                              void* d_out, int out_size)
{
    const float* q_in = (const float*)d_in[0];
    const float* k_in = (const float*)d_in[1];
    const float* v_in = (const float*)d_in[2];
    const float* Wq   = (const float*)d_in[3];
    const float* bq   = (const float*)d_in[4];
    const float* Wk   = (const float*)d_in[5];
    const float* bk   = (const float*)d_in[6];   // softmax-invariant: dropped
    const float* Wv   = (const float*)d_in[7];
    const float* bv   = (const float*)d_in[8];
    const float* E1   = (const float*)d_in[9];
    const float* E2   = (const float*)d_in[10];
    const float* Wo   = (const float*)d_in[11];
    const float* bo   = (const float*)d_in[12];
    (void)bk;

    float* outp = (float*)d_out;
    float* attn = outp + (size_t)BB * SS * DD;

    float *p_Wkp, *p_Bqk, *p_Wvp, *p_Wvo, *p_bqk, *p_bvp, *p_bvo, *p_zero, *p_rs;
    __half *bqk_h, *wvo_h, *p_qp, *p_kin, *p_vpT, *p_ath;
    cudaGetSymbolAddress((void**)&p_Wkp,  g_Wkp);
    cudaGetSymbolAddress((void**)&p_Bqk,  g_Bqk);
    cudaGetSymbolAddress((void**)&p_Wvp,  g_Wvp);
    cudaGetSymbolAddress((void**)&p_Wvo,  g_Wvo);
    cudaGetSymbolAddress((void**)&p_bqk,  g_bqk);
    cudaGetSymbolAddress((void**)&p_bvp,  g_bvp);
    cudaGetSymbolAddress((void**)&p_bvo,  g_bvo);
    cudaGetSymbolAddress((void**)&p_zero, g_zero512);
    cudaGetSymbolAddress((void**)&p_rs,   g_rowsum);
    cudaGetSymbolAddress((void**)&bqk_h,  g_Bqk_h);
    cudaGetSymbolAddress((void**)&wvo_h,  g_Wvo_h);
    cudaGetSymbolAddress((void**)&p_qp,   g_qp_h);
    cudaGetSymbolAddress((void**)&p_kin,  g_kin_h);
    cudaGetSymbolAddress((void**)&p_vpT,  g_vpT_h);
    cudaGetSymbolAddress((void**)&p_ath,  g_attn_h);

    cudaFuncSetAttribute(tgemm_f16_kernel, cudaFuncAttributeMaxDynamicSharedMemorySize, TG_SMEM);
    cudaFuncSetAttribute(tgemm_proj_kernel, cudaFuncAttributeMaxDynamicSharedMemorySize, TG_SMEM);

    const int M = BB * SS;
    const float scaling = 1.0f / sqrtf((float)DD);

    // --- zero rowsum accumulators (graph-capturable async memset) ---
    cudaMemsetAsync(p_rs, 0, (size_t)BB * SS * sizeof(float));

    // --- fold chain ---
    cvt_big_kernel<<<2048, 256>>>(k_in, p_kin, (long long)BB * SS * DD / 2);
    {
        FoldArgs f1;
        f1.A[0] = E1; f1.B[0] = Wk; f1.C[0] = p_Wkp; f1.tn[0] = 0;
        f1.A[1] = E2; f1.B[1] = Wv; f1.C[1] = p_Wvp; f1.tn[1] = 0;
        fold_gemm_kernel<<<dim3(8, 8, 2), 256>>>(f1);
    }
    {
        FoldArgs f2;
        f2.A[0] = p_Wkp; f2.B[0] = Wq;    f2.C[0] = p_Bqk; f2.tn[0] = 1;
        f2.A[1] = Wo;    f2.B[1] = p_Wvp; f2.C[1] = p_Wvo; f2.tn[1] = 0;
        fold_gemm_kernel<<<dim3(8, 8, 2), 256>>>(f2);
    }
    fuse_bias_kernel<<<DD, 256>>>(p_Wkp, bq, nullptr, p_bqk, 1);
    fuse_bias_kernel<<<DD, 256>>>(E2, bv, nullptr, p_bvp, 0);
    fuse_bias_kernel<<<DD, 256>>>(Wo, p_bvp, bo, p_bvo, 0);
    cvt2_kernel<<<dim3(128, 1, 2), 256>>>(p_Bqk, bqk_h, p_Wvo, wvo_h);

    // --- projections: q' = qin@Bqk^T + bqk ; vprojT = (v_in@Wvo^T)^T ---
    {
        ProjArgs pa;
        pa.A[0] = q_in; pa.Bh[0] = bqk_h; pa.out[0] = p_qp;  pa.bias[0] = p_bqk;  pa.trans[0] = 0;
        pa.A[1] = v_in; pa.Bh[1] = wvo_h; pa.out[1] = p_vpT; pa.bias[1] = p_zero; pa.trans[1] = 1;
        tgemm_proj_kernel<<<dim3(DD / 128, M / 128, 2), TG_THREADS, TG_SMEM>>>(pa, M, DD, DD);
    }

    // --- scores: attn <- exp(scaling * q'@kin^T) fp32 + fp16 copy + rowsums ---
    tgemm_f16_kernel<<<dim3(SS / 128, SS / 128, BB), TG_THREADS, TG_SMEM>>>(
        p_qp, p_kin, attn, p_ath, nullptr,
        p_rs, nullptr, nullptr, SS / 128,
        SS, SS, DD, scaling,
        (long long)SS * DD, (long long)SS * DD, (long long)SS * SS);

    // --- fused: out = (e @ vpT^T)/rowsum + bvo  (x<4) ; attn /= rowsum (x>=4) ---
    tgemm_f16_kernel<<<dim3(8, SS / 128, BB), TG_THREADS, TG_SMEM>>>(
        p_ath, p_vpT, outp, nullptr, p_bvo,
        nullptr, p_rs, attn, 4,
        SS, DD, SS, 1.0f,
        (long long)SS * SS, (long long)SS * DD, (long long)SS * DD);
}

// round 16
// speedup vs baseline: 1.0127x; 1.0127x over previous
#include <cuda_runtime.h>
#include <cuda_fp16.h>
#include <math.h>
#include <stdint.h>

#define BB 16
#define SS 2048
#define DD 512

// ---------------------------------------------------------------------------
// Scratch (device globals — no allocation allowed)
// ---------------------------------------------------------------------------
__device__ float g_Wkp[DD * DD];     // E1 @ Wk
__device__ float g_Bqk[DD * DD];     // Wkp^T @ Wq
__device__ float g_Wvp[DD * DD];     // E2 @ Wv
__device__ float g_Wvo[DD * DD];     // Wo @ Wvp
__device__ float g_bqk[DD];          // Wkp^T @ bq
__device__ float g_bvp[DD];          // E2 @ bv
__device__ float g_bvo[DD];          // Wo @ bvp + bo
__device__ float g_zero512[DD];

__device__ __half g_Bqk_h[DD * DD];
__device__ __half g_Wvo_h[DD * DD];
__device__ __half g_qp_h[(size_t)BB * SS * DD];
__device__ __half g_kin_h[(size_t)BB * SS * DD];
__device__ __half g_vpT_h[(size_t)BB * SS * DD];   // [b][n][t]

// ---------------------------------------------------------------------------
// helpers
// ---------------------------------------------------------------------------
__device__ __forceinline__ uint32_t smem_u32(const void* p) {
    uint32_t a;
    asm("{ .reg .u64 t; cvta.to.shared.u64 t, %1; cvt.u32.u64 %0, t; }"
        : "=r"(a) : "l"(p));
    return a;
}
__device__ __forceinline__ void cp_async16(uint32_t dst, const void* src) {
    asm volatile("cp.async.cg.shared.global [%0], [%1], 16;"
                 :: "r"(dst), "l"(src) : "memory");
}
__device__ __forceinline__ void cp_commit() {
    asm volatile("cp.async.commit_group;" ::: "memory");
}
__device__ __forceinline__ void cp_wait1() {
    asm volatile("cp.async.wait_group 1;" ::: "memory");
}
__device__ __forceinline__ void cp_wait0() {
    asm volatile("cp.async.wait_group 0;" ::: "memory");
}
__device__ __forceinline__ void ldsm4(uint32_t r[4], uint32_t addr) {
    asm volatile("ldmatrix.sync.aligned.m8n8.x4.shared.b16 {%0,%1,%2,%3}, [%4];"
                 : "=r"(r[0]), "=r"(r[1]), "=r"(r[2]), "=r"(r[3]) : "r"(addr));
}
__device__ __forceinline__ void mma_f16(float c[4], const uint32_t a[4],
                                        uint32_t b0, uint32_t b1) {
    asm volatile(
        "mma.sync.aligned.m16n8k16.row.col.f32.f16.f16.f32 "
        "{%0,%1,%2,%3}, {%4,%5,%6,%7}, {%8,%9}, {%0,%1,%2,%3};"
        : "+f"(c[0]), "+f"(c[1]), "+f"(c[2]), "+f"(c[3])
        : "r"(a[0]), "r"(a[1]), "r"(a[2]), "r"(a[3]), "r"(b0), "r"(b1));
}

// SMEM tile: 128 rows x 128B. swizzle: 16B chunk ch -> ch ^ (row&7)
__device__ __forceinline__ uint32_t tile_off(int row, int ch) {
    return (uint32_t)(row * 128 + ((ch ^ (row & 7)) * 16));
}

__device__ __forceinline__ void make_off2(int lane, int m0, int n0,
                                          uint32_t apre[4], uint32_t ax[4], int& ac0,
                                          uint32_t bpre[2], uint32_t bx[2], int& bc0)
{
#pragma unroll
    for (int i = 0; i < 4; i++) {
        const int r = m0 + i * 16 + (lane & 7) + ((lane >> 3) & 1) * 8;
        apre[i] = (uint32_t)(r * 128);
        ax[i]   = (uint32_t)(r & 7);
    }
    ac0 = lane >> 4;
#pragma unroll
    for (int j = 0; j < 2; j++) {
        const int r = n0 + j * 16 + (lane & 7) + ((lane >> 4) & 1) * 8;
        bpre[j] = (uint32_t)(r * 128);
        bx[j]   = (uint32_t)(r & 7);
    }
    bc0 = (lane >> 3) & 1;
}

// 64-K chunk = 4 k16 steps, double-buffered fragments
__device__ __forceinline__ void compute_chunk_f16(
    uint32_t stA, uint32_t stB,
    const uint32_t apre[4], const uint32_t ax[4], int ac0,
    const uint32_t bpre[2], const uint32_t bx[2], int bc0,
    float c[4][4][4])
{
    uint32_t a[2][4][4], b[2][2][4];
#pragma unroll
    for (int i = 0; i < 4; i++)
        ldsm4(a[0][i], stA + apre[i] + ((((uint32_t)ac0) ^ ax[i]) << 4));
#pragma unroll
    for (int j = 0; j < 2; j++)
        ldsm4(b[0][j], stB + bpre[j] + ((((uint32_t)bc0) ^ bx[j]) << 4));
#pragma unroll
    for (int ks = 0; ks < 4; ks++) {
        const int cur = ks & 1, nxt = cur ^ 1;
        if (ks < 3) {
            const uint32_t chA = (uint32_t)((ks + 1) * 2 + ac0);
            const uint32_t chB = (uint32_t)((ks + 1) * 2 + bc0);
#pragma unroll
            for (int i = 0; i < 4; i++)
                ldsm4(a[nxt][i], stA + apre[i] + ((chA ^ ax[i]) << 4));
#pragma unroll
            for (int j = 0; j < 2; j++)
                ldsm4(b[nxt][j], stB + bpre[j] + ((chB ^ bx[j]) << 4));
        }
#pragma unroll
        for (int i = 0; i < 4; i++)
#pragma unroll
            for (int j = 0; j < 4; j++)
                mma_f16(c[i][j], a[cur][i],
                        b[cur][j >> 1][(j & 1) * 2], b[cur][j >> 1][(j & 1) * 2 + 1]);
    }
}

#define TG_THREADS 256
#define TG_STAGE   32768
#define TG_SMEM    (3 * TG_STAGE)

// ---------------------------------------------------------------------------
// fp16 GEMM (scores): out = alpha * A @ B^T (+ bias). 128x128 tile,
// K-chunk 64, 3-stage cp.async, 8 warps, 2 CTA/SM.
// ---------------------------------------------------------------------------
__global__ __launch_bounds__(TG_THREADS, 2)
void tgemm_f16_kernel(const __half* __restrict__ A, const __half* __restrict__ Bm,
                      float* outF, __half* outH, const float* __restrict__ bias,
                      int M, int N, int K, float alpha,
                      long long sA, long long sB, long long sC)
{
    extern __shared__ char smem[];
    const uint32_t sb = smem_u32(smem);
    const int tid  = threadIdx.x;
    const int lane = tid & 31;
    const int wid  = tid >> 5;
    const int m0   = (wid & 1) * 64;
    const int n0   = (wid >> 1) * 32;

    const long long bz = blockIdx.z;
    A  += bz * sA;
    Bm += bz * sB;
    if (outF) outF += bz * sC;
    if (outH) outH += bz * sC;

    const int rowBase = blockIdx.y * 128;
    const int colBase = blockIdx.x * 128;

    int ldRow[4], ldCh[4];
    uint32_t ldOff[4];
#pragma unroll
    for (int i = 0; i < 4; i++) {
        const int u = tid + i * 256;
        ldRow[i] = u >> 3;
        ldCh[i]  = u & 7;
        ldOff[i] = tile_off(ldRow[i], ldCh[i]);
    }

    uint32_t apre[4], ax[4], bpre[2], bx[2];
    int ac0, bc0;
    make_off2(lane, m0, n0, apre, ax, ac0, bpre, bx, bc0);

    float c[4][4][4];
#pragma unroll
    for (int i = 0; i < 4; i++)
#pragma unroll
        for (int j = 0; j < 4; j++)
#pragma unroll
            for (int e = 0; e < 4; e++) c[i][j][e] = 0.0f;

    const int nc = K >> 6;

    auto load_stage = [&](int cidx) {
        const uint32_t dst = sb + (uint32_t)(cidx % 3) * TG_STAGE;
        const long long kb = (long long)cidx * 64;
#pragma unroll
        for (int i = 0; i < 4; i++) {
            const long long ea = (long long)(rowBase + ldRow[i]) * K + kb + ldCh[i] * 8;
            const long long eb = (long long)(colBase + ldRow[i]) * K + kb + ldCh[i] * 8;
            cp_async16(dst +          ldOff[i], A  + ea);
            cp_async16(dst + 16384u + ldOff[i], Bm + eb);
        }
        cp_commit();
    };

    load_stage(0);
    if (nc > 1) load_stage(1);

    for (int cidx = 0; cidx < nc; cidx++) {
        if (cidx + 1 < nc) cp_wait1(); else cp_wait0();
        __syncthreads();
        if (cidx + 2 < nc) load_stage(cidx + 2);
        const uint32_t st = sb + (uint32_t)(cidx % 3) * TG_STAGE;
        compute_chunk_f16(st, st + 16384u, apre, ax, ac0, bpre, bx, bc0, c);
    }
    __syncthreads();

    float* sf = (float*)smem;
#pragma unroll
    for (int i = 0; i < 4; i++) {
        const int r = m0 + i * 16 + (lane >> 2);
#pragma unroll
        for (int j = 0; j < 4; j++) {
            const int cc = n0 + j * 8 + (lane & 3) * 2;
            sf[r * 136 + cc]           = c[i][j][0];
            sf[r * 136 + cc + 1]       = c[i][j][1];
            sf[(r + 8) * 136 + cc]     = c[i][j][2];
            sf[(r + 8) * 136 + cc + 1] = c[i][j][3];
        }
    }
    __syncthreads();
#pragma unroll 4
    for (int e = tid; e < 128 * 128; e += TG_THREADS) {
        const int r = e >> 7, cc = e & 127;
        float v = sf[r * 136 + cc] * alpha;
        const int gc = colBase + cc;
        if (bias) v += bias[gc];
        const long long gi = (long long)(rowBase + r) * N + gc;
        if (outF) outF[gi] = v;
        if (outH) outH[gi] = __float2half_rn(v);
    }
}

// ---------------------------------------------------------------------------
// Batched fp32-A GEMM (attn@vp): A fp32 (cvt fp16 during STS), B fp16
// cp.async, fp32 output + bias. Layout: stage s = [s*32K, s*32K+16K) A,
// [s*32K+16K, (s+1)*32K) B.
// ---------------------------------------------------------------------------
__global__ __launch_bounds__(TG_THREADS, 2)
void tgemm_af32_kernel(const float* __restrict__ Abase,
                       const __half* __restrict__ Bbase,
                       float* __restrict__ outBase,
                       const float* __restrict__ bias,
                       int M, int N, int K,
                       long long sA, long long sB, long long sC)
{
    extern __shared__ char smem[];
    const uint32_t sb = smem_u32(smem);
    const int tid  = threadIdx.x;
    const int lane = tid & 31;
    const int wid  = tid >> 5;
    const int m0   = (wid & 1) * 64;
    const int n0   = (wid >> 1) * 32;

    const long long bz = blockIdx.z;
    const float* A  = Abase + bz * sA;
    const __half* Bh = Bbase + bz * sB;
    float* out = outBase + bz * sC;

    const int rowBase = blockIdx.y * 128;
    const int colBase = blockIdx.x * 128;

    int ldRow[4], ldCh[4];
    uint32_t ldOff[4];
#pragma unroll
    for (int i = 0; i < 4; i++) {
        const int u = tid + i * 256;
        ldRow[i] = u >> 3;
        ldCh[i]  = u & 7;
        ldOff[i] = tile_off(ldRow[i], ldCh[i]);
    }

    uint32_t apre[4], ax[4], bpre[2], bx[2];
    int ac0, bc0;
    make_off2(lane, m0, n0, apre, ax, ac0, bpre, bx, bc0);

    float c[4][4][4];
#pragma unroll
    for (int i = 0; i < 4; i++)
#pragma unroll
        for (int j = 0; j < 4; j++)
#pragma unroll
            for (int e = 0; e < 4; e++) c[i][j][e] = 0.0f;

    const int nc = K >> 6;

    auto issueB = [&](int cidx) {
        const uint32_t dst = sb + 16384u + (uint32_t)(cidx % 3) * TG_STAGE;
        const long long kb = (long long)cidx * 64;
#pragma unroll
        for (int i = 0; i < 4; i++) {
            const long long eb = (long long)(colBase + ldRow[i]) * K + kb + ldCh[i] * 8;
            cp_async16(dst + ldOff[i], Bh + eb);
        }
        cp_commit();
    };
    auto ldgA = [&](int cidx, float4 ar[4][2]) {
        const long long kb = (long long)cidx * 64;
#pragma unroll
        for (int i = 0; i < 4; i++) {
            const float* p = A + (long long)(rowBase + ldRow[i]) * K + kb + ldCh[i] * 8;
            ar[i][0] = *(const float4*)(p);
            ar[i][1] = *(const float4*)(p + 4);
        }
    };
    auto stsA = [&](int cidx, const float4 ar[4][2]) {
        char* base = smem + (cidx % 3) * TG_STAGE;
#pragma unroll
        for (int i = 0; i < 4; i++) {
            uint4 t;
            __half2 h0 = __floats2half2_rn(ar[i][0].x, ar[i][0].y);
            __half2 h1 = __floats2half2_rn(ar[i][0].z, ar[i][0].w);
            __half2 h2 = __floats2half2_rn(ar[i][1].x, ar[i][1].y);
            __half2 h3 = __floats2half2_rn(ar[i][1].z, ar[i][1].w);
            t.x = *reinterpret_cast<uint32_t*>(&h0);
            t.y = *reinterpret_cast<uint32_t*>(&h1);
            t.z = *reinterpret_cast<uint32_t*>(&h2);
            t.w = *reinterpret_cast<uint32_t*>(&h3);
            *(uint4*)(base + ldOff[i]) = t;
        }
    };

    float4 ar[4][2];
    ldgA(0, ar);
    issueB(0);
    if (nc > 1) issueB(1);
    stsA(0, ar);
    if (nc > 1) ldgA(1, ar);

    for (int cidx = 0; cidx < nc; cidx++) {
        if (cidx + 1 < nc) cp_wait1(); else cp_wait0();
        __syncthreads();
        if (cidx + 2 < nc) issueB(cidx + 2);
        if (cidx + 1 < nc) stsA(cidx + 1, ar);
        if (cidx + 2 < nc) ldgA(cidx + 2, ar);
        const uint32_t st = sb + (uint32_t)(cidx % 3) * TG_STAGE;
        compute_chunk_f16(st, st + 16384u, apre, ax, ac0, bpre, bx, bc0, c);
    }
    __syncthreads();

    float* sf = (float*)smem;
#pragma unroll
    for (int i = 0; i < 4; i++) {
        const int r = m0 + i * 16 + (lane >> 2);
#pragma unroll
        for (int j = 0; j < 4; j++) {
            const int cc = n0 + j * 8 + (lane & 3) * 2;
            sf[r * 136 + cc]           = c[i][j][0];
            sf[r * 136 + cc + 1]       = c[i][j][1];
            sf[(r + 8) * 136 + cc]     = c[i][j][2];
            sf[(r + 8) * 136 + cc + 1] = c[i][j][3];
        }
    }
    __syncthreads();
#pragma unroll 4
    for (int e = tid; e < 128 * 128; e += TG_THREADS) {
        const int r = e >> 7, cc = e & 127;
        const int gc = colBase + cc;
        float v = sf[r * 136 + cc] + bias[gc];
        out[(long long)(rowBase + r) * N + gc] = v;
    }
}

// ---------------------------------------------------------------------------
// Merged projection GEMM (z = 0: q' ; 1: vproj(trans)).
// ---------------------------------------------------------------------------
struct ProjArgs {
    const float*  A[2];
    const __half* Bh[2];
    __half*       out[2];
    const float*  bias[2];
    int           trans[2];
};

__global__ __launch_bounds__(TG_THREADS, 2)
void tgemm_proj_kernel(ProjArgs pa, int M, int N, int K)
{
    extern __shared__ char smem[];
    const uint32_t sb = smem_u32(smem);
    const int tid  = threadIdx.x;
    const int lane = tid & 31;
    const int wid  = tid >> 5;
    const int m0   = (wid & 1) * 64;
    const int n0   = (wid >> 1) * 32;
    const int z    = blockIdx.z;

    const float* A    = pa.A[z];
    const __half* Bh  = pa.Bh[z];
    __half* out       = pa.out[z];
    const float* bias = pa.bias[z];
    const int transOut = pa.trans[z];

    const int rowBase = blockIdx.y * 128;
    const int colBase = blockIdx.x * 128;

    int ldRow[4], ldCh[4];
    uint32_t ldOff[4];
#pragma unroll
    for (int i = 0; i < 4; i++) {
        const int u = tid + i * 256;
        ldRow[i] = u >> 3;
        ldCh[i]  = u & 7;
        ldOff[i] = tile_off(ldRow[i], ldCh[i]);
    }

    uint32_t apre[4], ax[4], bpre[2], bx[2];
    int ac0, bc0;
    make_off2(lane, m0, n0, apre, ax, ac0, bpre, bx, bc0);

    float c[4][4][4];
#pragma unroll
    for (int i = 0; i < 4; i++)
#pragma unroll
        for (int j = 0; j < 4; j++)
#pragma unroll
            for (int e = 0; e < 4; e++) c[i][j][e] = 0.0f;

    const int nc = K >> 6;

    auto issueB = [&](int cidx) {
        const uint32_t dst = sb + 16384u + (uint32_t)(cidx % 3) * TG_STAGE;
        const long long kb = (long long)cidx * 64;
#pragma unroll
        for (int i = 0; i < 4; i++) {
            const long long eb = (long long)(colBase + ldRow[i]) * K + kb + ldCh[i] * 8;
            cp_async16(dst + ldOff[i], Bh + eb);
        }
        cp_commit();
    };
    auto ldgA = [&](int cidx, float4 ar[4][2]) {
        const long long kb = (long long)cidx * 64;
#pragma unroll
        for (int i = 0; i < 4; i++) {
            const float* p = A + (long long)(rowBase + ldRow[i]) * K + kb + ldCh[i] * 8;
            ar[i][0] = *(const float4*)(p);
            ar[i][1] = *(const float4*)(p + 4);
        }
    };
    auto stsA = [&](int cidx, const float4 ar[4][2]) {
        char* base = smem + (cidx % 3) * TG_STAGE;
#pragma unroll
        for (int i = 0; i < 4; i++) {
            uint4 t;
            __half2 h0 = __floats2half2_rn(ar[i][0].x, ar[i][0].y);
            __half2 h1 = __floats2half2_rn(ar[i][0].z, ar[i][0].w);
            __half2 h2 = __floats2half2_rn(ar[i][1].x, ar[i][1].y);
            __half2 h3 = __floats2half2_rn(ar[i][1].z, ar[i][1].w);
            t.x = *reinterpret_cast<uint32_t*>(&h0);
            t.y = *reinterpret_cast<uint32_t*>(&h1);
            t.z = *reinterpret_cast<uint32_t*>(&h2);
            t.w = *reinterpret_cast<uint32_t*>(&h3);
            *(uint4*)(base + ldOff[i]) = t;
        }
    };

    float4 ar[4][2];
    ldgA(0, ar);
    issueB(0);
    if (nc > 1) issueB(1);
    stsA(0, ar);
    if (nc > 1) ldgA(1, ar);

    for (int cidx = 0; cidx < nc; cidx++) {
        if (cidx + 1 < nc) cp_wait1(); else cp_wait0();
        __syncthreads();
        if (cidx + 2 < nc) issueB(cidx + 2);
        if (cidx + 1 < nc) stsA(cidx + 1, ar);
        if (cidx + 2 < nc) ldgA(cidx + 2, ar);
        const uint32_t st = sb + (uint32_t)(cidx % 3) * TG_STAGE;
        compute_chunk_f16(st, st + 16384u, apre, ax, ac0, bpre, bx, bc0, c);
    }
    __syncthreads();

    float* sf = (float*)smem;
#pragma unroll
    for (int i = 0; i < 4; i++) {
        const int r = m0 + i * 16 + (lane >> 2);
#pragma unroll
        for (int j = 0; j < 4; j++) {
            const int cc = n0 + j * 8 + (lane & 3) * 2;
            sf[r * 136 + cc]           = c[i][j][0];
            sf[r * 136 + cc + 1]       = c[i][j][1];
            sf[(r + 8) * 136 + cc]     = c[i][j][2];
            sf[(r + 8) * 136 + cc + 1] = c[i][j][3];
        }
    }
    __syncthreads();
#pragma unroll 4
    for (int e = tid; e < 128 * 128; e += TG_THREADS) {
        int r, cc;
        if (transOut) { r = e & 127; cc = e >> 7; }
        else          { r = e >> 7;  cc = e & 127; }
        float v = sf[r * 136 + cc] + bias[colBase + cc];
        long long gi;
        if (transOut) {
            const int grow = rowBase + r;
            gi = (long long)(grow >> 11) * ((long long)DD * SS)
               + (long long)(colBase + cc) * SS + (grow & 2047);
        } else {
            gi = (long long)(rowBase + r) * N + colBase + cc;
        }
        out[gi] = __float2half_rn(v);
    }
}

// ---------------------------------------------------------------------------
// Fold GEMM (512^3, fp32): 64x64 tile, BK=16. grid (8,8,2). tn: C = A^T @ B.
// ---------------------------------------------------------------------------
struct FoldArgs {
    const float* A[2];
    const float* B[2];
    float*       C[2];
    int          tn[2];
};

__global__ __launch_bounds__(256)
void fold_gemm_kernel(FoldArgs fa)
{
    const int z = blockIdx.z;
    const float* A = fa.A[z];
    const float* B = fa.B[z];
    float* C = fa.C[z];
    const int tn = fa.tn[z];

    __shared__ float As[16][68];
    __shared__ float Bs[16][68];
    const int tid = threadIdx.x;
    const int tx = tid & 15, ty = tid >> 4;
    const int m0 = blockIdx.y * 64, n0 = blockIdx.x * 64;

    float acc[4][4];
#pragma unroll
    for (int i = 0; i < 4; i++)
#pragma unroll
        for (int j = 0; j < 4; j++) acc[i][j] = 0.0f;

    for (int k0 = 0; k0 < DD; k0 += 16) {
        if (tn) {
            const int kr = tid >> 4, mc = (tid & 15) * 4;
            float4 a = *(const float4*)(A + (long long)(k0 + kr) * DD + m0 + mc);
            *(float4*)&As[kr][mc] = a;
        } else {
            const int r = tid >> 2, kc = (tid & 3) * 4;
            float4 a = *(const float4*)(A + (long long)(m0 + r) * DD + k0 + kc);
            As[kc + 0][r] = a.x; As[kc + 1][r] = a.y;
            As[kc + 2][r] = a.z; As[kc + 3][r] = a.w;
        }
        {
            const int kr = tid >> 4, ncc = (tid & 15) * 4;
            float4 b = *(const float4*)(B + (long long)(k0 + kr) * DD + n0 + ncc);
            *(float4*)&Bs[kr][ncc] = b;
        }
        __syncthreads();
#pragma unroll
        for (int k = 0; k < 16; k++) {
            float4 a = *(const float4*)&As[k][ty * 4];
            float4 b = *(const float4*)&Bs[k][tx * 4];
            float av[4] = {a.x, a.y, a.z, a.w};
            float bv[4] = {b.x, b.y, b.z, b.w};
#pragma unroll
            for (int i = 0; i < 4; i++)
#pragma unroll
                for (int j = 0; j < 4; j++)
                    acc[i][j] = fmaf(av[i], bv[j], acc[i][j]);
        }
        __syncthreads();
    }
#pragma unroll
    for (int i = 0; i < 4; i++) {
        float4 v = {acc[i][0], acc[i][1], acc[i][2], acc[i][3]};
        *(float4*)(C + (long long)(m0 + ty * 4 + i) * DD + n0 + tx * 4) = v;
    }
}

// out[p] = sum_d E'[p,d]*b[d] + (add ? add[p] : 0); transE: E'[p,d] = E[d,p]
__global__ void fuse_bias_kernel(const float* __restrict__ E,
                                 const float* __restrict__ b,
                                 const float* __restrict__ add,
                                 float* __restrict__ out, int transE)
{
    __shared__ float red[8];
    const int p = blockIdx.x;
    float s = 0.0f;
    for (int d = threadIdx.x; d < DD; d += 256) {
        float e = transE ? E[(long long)d * DD + p] : E[(long long)p * DD + d];
        s = fmaf(e, b[d], s);
    }
#pragma unroll
    for (int off = 16; off > 0; off >>= 1) s += __shfl_xor_sync(0xffffffffu, s, off);
    if ((threadIdx.x & 31) == 0) red[threadIdx.x >> 5] = s;
    __syncthreads();
    if (threadIdx.x == 0) {
        float t = 0.0f;
#pragma unroll
        for (int i = 0; i < 8; i++) t += red[i];
        out[p] = t + (add ? add[p] : 0.0f);
    }
}

// convert 2 weight matrices fp32 -> fp16
__global__ void cvt2_kernel(const float* __restrict__ s0, __half* __restrict__ d0,
                            const float* __restrict__ s1, __half* __restrict__ d1)
{
    const float* x = blockIdx.z ? s1 : s0;
    __half* y      = blockIdx.z ? d1 : d0;
    const int n = DD * DD;
    for (int i = blockIdx.x * blockDim.x + threadIdx.x; i < n;
         i += gridDim.x * blockDim.x)
        y[i] = __float2half_rn(x[i]);
}

// big fp32 -> fp16 convert (k_in)
__global__ void cvt_big_kernel(const float* __restrict__ x, __half* __restrict__ y,
                               long long n)
{
    long long i = (long long)blockIdx.x * blockDim.x + threadIdx.x;
    const long long stride = (long long)gridDim.x * blockDim.x;
    for (; i < n; i += stride) {
        float2 v = *(const float2*)(x + i * 2);
        __half2 h = __floats2half2_rn(v.x, v.y);
        *(__half2*)(y + i * 2) = h;
    }
}

// softmax rows of 2048 in place (fp32 only) — vectorized
__global__ __launch_bounds__(256)
void softmax2048_kernel(float* __restrict__ data)
{
    const size_t base = (size_t)blockIdx.x * 2048;
    float4* row4 = (float4*)(data + base);
    const int tid = threadIdx.x;
    __shared__ float red[8];

    float4 v0 = row4[tid * 2];
    float4 v1 = row4[tid * 2 + 1];
    float v[8] = {v0.x, v0.y, v0.z, v0.w, v1.x, v1.y, v1.z, v1.w};

    float m = -3.4e38f;
#pragma unroll
    for (int i = 0; i < 8; i++) m = fmaxf(m, v[i]);
#pragma unroll
    for (int o = 16; o > 0; o >>= 1) m = fmaxf(m, __shfl_xor_sync(0xffffffffu, m, o));
    if ((tid & 31) == 0) red[tid >> 5] = m;
    __syncthreads();
    float bm = red[0];
#pragma unroll
    for (int i = 1; i < 8; i++) bm = fmaxf(bm, red[i]);
    __syncthreads();

    float s = 0.0f;
#pragma unroll
    for (int i = 0; i < 8; i++) { v[i] = __expf(v[i] - bm); s += v[i]; }
#pragma unroll
    for (int o = 16; o > 0; o >>= 1) s += __shfl_xor_sync(0xffffffffu, s, o);
    if ((tid & 31) == 0) red[tid >> 5] = s;
    __syncthreads();
    float bs = 0.0f;
#pragma unroll
    for (int i = 0; i < 8; i++) bs += red[i];

    const float inv = 1.0f / bs;
#pragma unroll
    for (int i = 0; i < 8; i++) v[i] *= inv;

    row4[tid * 2]     = make_float4(v[0], v[1], v[2], v[3]);
    row4[tid * 2 + 1] = make_float4(v[4], v[5], v[6], v[7]);
}

// ---------------------------------------------------------------------------
// Launch
// ---------------------------------------------------------------------------
extern "C" void kernel_launch(void* const* d_in, const int* in_sizes, int n_in,
                              void* d_out, int out_size)
{
    const float* q_in = (const float*)d_in[0];
    const float* k_in = (const float*)d_in[1];
    const float* v_in = (const float*)d_in[2];
    const float* Wq   = (const float*)d_in[3];
    const float* bq   = (const float*)d_in[4];
    const float* Wk   = (const float*)d_in[5];
    const float* bk   = (const float*)d_in[6];   // softmax-invariant: dropped
    const float* Wv   = (const float*)d_in[7];
    const float* bv   = (const float*)d_in[8];
    const float* E1   = (const float*)d_in[9];
    const float* E2   = (const float*)d_in[10];
    const float* Wo   = (const float*)d_in[11];
    const float* bo   = (const float*)d_in[12];
    (void)bk;

    float* outp = (float*)d_out;
    float* attn = outp + (size_t)BB * SS * DD;

    float *p_Wkp, *p_Bqk, *p_Wvp, *p_Wvo, *p_bqk, *p_bvp, *p_bvo, *p_zero;
    __half *bqk_h, *wvo_h, *p_qp, *p_kin, *p_vpT;
    cudaGetSymbolAddress((void**)&p_Wkp,  g_Wkp);
    cudaGetSymbolAddress((void**)&p_Bqk,  g_Bqk);
    cudaGetSymbolAddress((void**)&p_Wvp,  g_Wvp);
    cudaGetSymbolAddress((void**)&p_Wvo,  g_Wvo);
    cudaGetSymbolAddress((void**)&p_bqk,  g_bqk);
    cudaGetSymbolAddress((void**)&p_bvp,  g_bvp);
    cudaGetSymbolAddress((void**)&p_bvo,  g_bvo);
    cudaGetSymbolAddress((void**)&p_zero, g_zero512);
    cudaGetSymbolAddress((void**)&bqk_h,  g_Bqk_h);
    cudaGetSymbolAddress((void**)&wvo_h,  g_Wvo_h);
    cudaGetSymbolAddress((void**)&p_qp,   g_qp_h);
    cudaGetSymbolAddress((void**)&p_kin,  g_kin_h);
    cudaGetSymbolAddress((void**)&p_vpT,  g_vpT_h);

    cudaFuncSetAttribute(tgemm_f16_kernel, cudaFuncAttributeMaxDynamicSharedMemorySize, TG_SMEM);
    cudaFuncSetAttribute(tgemm_af32_kernel, cudaFuncAttributeMaxDynamicSharedMemorySize, TG_SMEM);
    cudaFuncSetAttribute(tgemm_proj_kernel, cudaFuncAttributeMaxDynamicSharedMemorySize, TG_SMEM);

    const int M = BB * SS;
    const float scaling = 1.0f / sqrtf((float)DD);

    // --- fold chain ---
    cvt_big_kernel<<<2048, 256>>>(k_in, p_kin, (long long)BB * SS * DD / 2);
    {
        FoldArgs f1;
        f1.A[0] = E1; f1.B[0] = Wk; f1.C[0] = p_Wkp; f1.tn[0] = 0;
        f1.A[1] = E2; f1.B[1] = Wv; f1.C[1] = p_Wvp; f1.tn[1] = 0;
        fold_gemm_kernel<<<dim3(8, 8, 2), 256>>>(f1);
    }
    {
        FoldArgs f2;
        f2.A[0] = p_Wkp; f2.B[0] = Wq;    f2.C[0] = p_Bqk; f2.tn[0] = 1;
        f2.A[1] = Wo;    f2.B[1] = p_Wvp; f2.C[1] = p_Wvo; f2.tn[1] = 0;
        fold_gemm_kernel<<<dim3(8, 8, 2), 256>>>(f2);
    }
    fuse_bias_kernel<<<DD, 256>>>(p_Wkp, bq, nullptr, p_bqk, 1);
    fuse_bias_kernel<<<DD, 256>>>(E2, bv, nullptr, p_bvp, 0);
    fuse_bias_kernel<<<DD, 256>>>(Wo, p_bvp, bo, p_bvo, 0);
    cvt2_kernel<<<dim3(128, 1, 2), 256>>>(p_Bqk, bqk_h, p_Wvo, wvo_h);

    // --- projections: q' = qin@Bqk^T + bqk ; vprojT = (v_in@Wvo^T)^T ---
    {
        ProjArgs pa;
        pa.A[0] = q_in; pa.Bh[0] = bqk_h; pa.out[0] = p_qp;  pa.bias[0] = p_bqk;  pa.trans[0] = 0;
        pa.A[1] = v_in; pa.Bh[1] = wvo_h; pa.out[1] = p_vpT; pa.bias[1] = p_zero; pa.trans[1] = 1;
        tgemm_proj_kernel<<<dim3(DD / 128, M / 128, 2), TG_THREADS, TG_SMEM>>>(pa, M, DD, DD);
    }

    // --- scores = scaling * q' @ kin^T -> attn region fp32 ---
    tgemm_f16_kernel<<<dim3(SS / 128, SS / 128, BB), TG_THREADS, TG_SMEM>>>(
        p_qp, p_kin, attn, nullptr, nullptr, SS, SS, DD, scaling,
        (long long)SS * DD, (long long)SS * DD, (long long)SS * SS);

    // --- softmax in place (fp32 only) ---
    softmax2048_kernel<<<BB * SS, 256>>>(attn);

    // --- out = attn(fp32, cvt in-kernel) @ vpT^T + bvo ---
    tgemm_af32_kernel<<<dim3(DD / 128, SS / 128, BB), TG_THREADS, TG_SMEM>>>(
        attn, p_vpT, outp, p_bvo, SS, DD, SS,
        (long long)SS * SS, (long long)SS * DD, (long long)SS * DD);
}

// round 17
// speedup vs baseline: 1.0906x; 1.0769x over previous
#include <cuda_runtime.h>
#include <cuda_fp16.h>
#include <math.h>
#include <stdint.h>

#define BB 16
#define SS 2048
#define DD 512

// ---------------------------------------------------------------------------
// Scratch (device globals — no allocation allowed)
// ---------------------------------------------------------------------------
__device__ float g_Wkp[DD * DD];     // E1 @ Wk
__device__ float g_Bqk[DD * DD];     // Wkp^T @ Wq
__device__ float g_Wvp[DD * DD];     // E2 @ Wv
__device__ float g_Wvo[DD * DD];     // Wo @ Wvp
__device__ float g_bqk[DD];          // Wkp^T @ bq
__device__ float g_bvp[DD];          // E2 @ bv
__device__ float g_bvo[DD];          // Wo @ bvp + bo
__device__ float g_zero512[DD];

__device__ __half g_Bqk_h[DD * DD];
__device__ __half g_Wvo_h[DD * DD];
__device__ __half g_qp_h[(size_t)BB * SS * DD];
__device__ __half g_kin_h[(size_t)BB * SS * DD];
__device__ __half g_vpT_h[(size_t)BB * SS * DD];   // [b][n][t]
__device__ __half g_attn_h[(size_t)BB * SS * SS];  // fp16 attn copy

// ---------------------------------------------------------------------------
// helpers
// ---------------------------------------------------------------------------
__device__ __forceinline__ uint32_t smem_u32(const void* p) {
    uint32_t a;
    asm("{ .reg .u64 t; cvta.to.shared.u64 t, %1; cvt.u32.u64 %0, t; }"
        : "=r"(a) : "l"(p));
    return a;
}
__device__ __forceinline__ void cp_async16(uint32_t dst, const void* src) {
    asm volatile("cp.async.cg.shared.global [%0], [%1], 16;"
                 :: "r"(dst), "l"(src) : "memory");
}
__device__ __forceinline__ void cp_commit() {
    asm volatile("cp.async.commit_group;" ::: "memory");
}
__device__ __forceinline__ void cp_wait1() {
    asm volatile("cp.async.wait_group 1;" ::: "memory");
}
__device__ __forceinline__ void cp_wait0() {
    asm volatile("cp.async.wait_group 0;" ::: "memory");
}
__device__ __forceinline__ void ldsm4(uint32_t r[4], uint32_t addr) {
    asm volatile("ldmatrix.sync.aligned.m8n8.x4.shared.b16 {%0,%1,%2,%3}, [%4];"
                 : "=r"(r[0]), "=r"(r[1]), "=r"(r[2]), "=r"(r[3]) : "r"(addr));
}
__device__ __forceinline__ void mma_f16(float c[4], const uint32_t a[4],
                                        uint32_t b0, uint32_t b1) {
    asm volatile(
        "mma.sync.aligned.m16n8k16.row.col.f32.f16.f16.f32 "
        "{%0,%1,%2,%3}, {%4,%5,%6,%7}, {%8,%9}, {%0,%1,%2,%3};"
        : "+f"(c[0]), "+f"(c[1]), "+f"(c[2]), "+f"(c[3])
        : "r"(a[0]), "r"(a[1]), "r"(a[2]), "r"(a[3]), "r"(b0), "r"(b1));
}

// SMEM tile: 128 rows x 128B. swizzle: 16B chunk ch -> ch ^ (row&7)
__device__ __forceinline__ uint32_t tile_off(int row, int ch) {
    return (uint32_t)(row * 128 + ((ch ^ (row & 7)) * 16));
}

__device__ __forceinline__ void make_off2(int lane, int m0, int n0,
                                          uint32_t apre[4], uint32_t ax[4], int& ac0,
                                          uint32_t bpre[2], uint32_t bx[2], int& bc0)
{
#pragma unroll
    for (int i = 0; i < 4; i++) {
        const int r = m0 + i * 16 + (lane & 7) + ((lane >> 3) & 1) * 8;
        apre[i] = (uint32_t)(r * 128);
        ax[i]   = (uint32_t)(r & 7);
    }
    ac0 = lane >> 4;
#pragma unroll
    for (int j = 0; j < 2; j++) {
        const int r = n0 + j * 16 + (lane & 7) + ((lane >> 4) & 1) * 8;
        bpre[j] = (uint32_t)(r * 128);
        bx[j]   = (uint32_t)(r & 7);
    }
    bc0 = (lane >> 3) & 1;
}

// 64-K chunk = 4 k16 steps, double-buffered fragments
__device__ __forceinline__ void compute_chunk_f16(
    uint32_t stA, uint32_t stB,
    const uint32_t apre[4], const uint32_t ax[4], int ac0,
    const uint32_t bpre[2], const uint32_t bx[2], int bc0,
    float c[4][4][4])
{
    uint32_t a[2][4][4], b[2][2][4];
#pragma unroll
    for (int i = 0; i < 4; i++)
        ldsm4(a[0][i], stA + apre[i] + ((((uint32_t)ac0) ^ ax[i]) << 4));
#pragma unroll
    for (int j = 0; j < 2; j++)
        ldsm4(b[0][j], stB + bpre[j] + ((((uint32_t)bc0) ^ bx[j]) << 4));
#pragma unroll
    for (int ks = 0; ks < 4; ks++) {
        const int cur = ks & 1, nxt = cur ^ 1;
        if (ks < 3) {
            const uint32_t chA = (uint32_t)((ks + 1) * 2 + ac0);
            const uint32_t chB = (uint32_t)((ks + 1) * 2 + bc0);
#pragma unroll
            for (int i = 0; i < 4; i++)
                ldsm4(a[nxt][i], stA + apre[i] + ((chA ^ ax[i]) << 4));
#pragma unroll
            for (int j = 0; j < 2; j++)
                ldsm4(b[nxt][j], stB + bpre[j] + ((chB ^ bx[j]) << 4));
        }
#pragma unroll
        for (int i = 0; i < 4; i++)
#pragma unroll
            for (int j = 0; j < 4; j++)
                mma_f16(c[i][j], a[cur][i],
                        b[cur][j >> 1][(j & 1) * 2], b[cur][j >> 1][(j & 1) * 2 + 1]);
    }
}

#define TG_THREADS 256
#define TG_STAGE   32768
#define TG_SMEM    (3 * TG_STAGE)

// ---------------------------------------------------------------------------
// fp16 GEMM (scores): out = alpha * A @ B^T. 128x128 tile, K-chunk 64,
// 3-stage cp.async, 8 warps, 2 CTA/SM.
// ---------------------------------------------------------------------------
__global__ __launch_bounds__(TG_THREADS, 2)
void tgemm_f16_kernel(const __half* __restrict__ A, const __half* __restrict__ Bm,
                      float* outF, __half* outH, const float* __restrict__ bias,
                      int M, int N, int K, float alpha,
                      long long sA, long long sB, long long sC)
{
    extern __shared__ char smem[];
    const uint32_t sb = smem_u32(smem);
    const int tid  = threadIdx.x;
    const int lane = tid & 31;
    const int wid  = tid >> 5;
    const int m0   = (wid & 1) * 64;
    const int n0   = (wid >> 1) * 32;

    const long long bz = blockIdx.z;
    A  += bz * sA;
    Bm += bz * sB;
    if (outF) outF += bz * sC;
    if (outH) outH += bz * sC;

    const int rowBase = blockIdx.y * 128;
    const int colBase = blockIdx.x * 128;

    int ldRow[4], ldCh[4];
    uint32_t ldOff[4];
#pragma unroll
    for (int i = 0; i < 4; i++) {
        const int u = tid + i * 256;
        ldRow[i] = u >> 3;
        ldCh[i]  = u & 7;
        ldOff[i] = tile_off(ldRow[i], ldCh[i]);
    }

    uint32_t apre[4], ax[4], bpre[2], bx[2];
    int ac0, bc0;
    make_off2(lane, m0, n0, apre, ax, ac0, bpre, bx, bc0);

    float c[4][4][4];
#pragma unroll
    for (int i = 0; i < 4; i++)
#pragma unroll
        for (int j = 0; j < 4; j++)
#pragma unroll
            for (int e = 0; e < 4; e++) c[i][j][e] = 0.0f;

    const int nc = K >> 6;

    auto load_stage = [&](int cidx) {
        const uint32_t dst = sb + (uint32_t)(cidx % 3) * TG_STAGE;
        const long long kb = (long long)cidx * 64;
#pragma unroll
        for (int i = 0; i < 4; i++) {
            const long long ea = (long long)(rowBase + ldRow[i]) * K + kb + ldCh[i] * 8;
            const long long eb = (long long)(colBase + ldRow[i]) * K + kb + ldCh[i] * 8;
            cp_async16(dst +          ldOff[i], A  + ea);
            cp_async16(dst + 16384u + ldOff[i], Bm + eb);
        }
        cp_commit();
    };

    load_stage(0);
    if (nc > 1) load_stage(1);

    for (int cidx = 0; cidx < nc; cidx++) {
        if (cidx + 1 < nc) cp_wait1(); else cp_wait0();
        __syncthreads();
        if (cidx + 2 < nc) load_stage(cidx + 2);
        const uint32_t st = sb + (uint32_t)(cidx % 3) * TG_STAGE;
        compute_chunk_f16(st, st + 16384u, apre, ax, ac0, bpre, bx, bc0, c);
    }
    __syncthreads();

    float* sf = (float*)smem;
#pragma unroll
    for (int i = 0; i < 4; i++) {
        const int r = m0 + i * 16 + (lane >> 2);
#pragma unroll
        for (int j = 0; j < 4; j++) {
            const int cc = n0 + j * 8 + (lane & 3) * 2;
            sf[r * 136 + cc]           = c[i][j][0];
            sf[r * 136 + cc + 1]       = c[i][j][1];
            sf[(r + 8) * 136 + cc]     = c[i][j][2];
            sf[(r + 8) * 136 + cc + 1] = c[i][j][3];
        }
    }
    __syncthreads();
#pragma unroll 4
    for (int e = tid; e < 128 * 128; e += TG_THREADS) {
        const int r = e >> 7, cc = e & 127;
        float v = sf[r * 136 + cc] * alpha;
        const int gc = colBase + cc;
        if (bias) v += bias[gc];
        const long long gi = (long long)(rowBase + r) * N + gc;
        if (outF) outF[gi] = v;
        if (outH) outH[gi] = __float2half_rn(v);
    }
}

// ---------------------------------------------------------------------------
// Persistent fp16 GEMM for attn@vp: out = A @ B^T + bias, fp32 out.
// Fixed shape M=SS, N=DD, K=SS, batch BB. 1024 tiles strided over gridDim.x
// CTAs (x-fastest order for A-row L2 reuse).
// ---------------------------------------------------------------------------
#define AV_TILES (BB * (SS / 128) * (DD / 128))   // 1024

__global__ __launch_bounds__(TG_THREADS, 2)
void tgemm_av_persist_kernel(const __half* __restrict__ A,
                             const __half* __restrict__ Bm,
                             float* __restrict__ out,
                             const float* __restrict__ bias)
{
    extern __shared__ char smem[];
    const uint32_t sb = smem_u32(smem);
    const int tid  = threadIdx.x;
    const int lane = tid & 31;
    const int wid  = tid >> 5;
    const int m0   = (wid & 1) * 64;
    const int n0   = (wid >> 1) * 32;

    // tile-invariant per-thread geometry
    int ldRow[4], ldCh[4];
    uint32_t ldOff[4];
#pragma unroll
    for (int i = 0; i < 4; i++) {
        const int u = tid + i * 256;
        ldRow[i] = u >> 3;
        ldCh[i]  = u & 7;
        ldOff[i] = tile_off(ldRow[i], ldCh[i]);
    }
    uint32_t apre[4], ax[4], bpre[2], bx[2];
    int ac0, bc0;
    make_off2(lane, m0, n0, apre, ax, ac0, bpre, bx, bc0);

    const int nc = SS >> 6;   // 32 chunks of K=64

    for (int t = blockIdx.x; t < AV_TILES; t += gridDim.x) {
        const int tx = t & 3;               // N tile (x fastest: A-row L2 reuse)
        const int ty = (t >> 2) & 15;       // M tile
        const int tz = t >> 6;              // batch
        const int rowBase = ty * 128;
        const int colBase = tx * 128;
        const __half* At = A + (long long)tz * SS * SS;
        const __half* Bt = Bm + (long long)tz * SS * DD;
        float* outT = out + (long long)tz * SS * DD;

        float c[4][4][4];
#pragma unroll
        for (int i = 0; i < 4; i++)
#pragma unroll
            for (int j = 0; j < 4; j++)
#pragma unroll
                for (int e = 0; e < 4; e++) c[i][j][e] = 0.0f;

        auto load_stage = [&](int cidx) {
            const uint32_t dst = sb + (uint32_t)(cidx % 3) * TG_STAGE;
            const long long kb = (long long)cidx * 64;
#pragma unroll
            for (int i = 0; i < 4; i++) {
                const long long ea = (long long)(rowBase + ldRow[i]) * SS + kb + ldCh[i] * 8;
                const long long eb = (long long)(colBase + ldRow[i]) * SS + kb + ldCh[i] * 8;
                cp_async16(dst +          ldOff[i], At + ea);
                cp_async16(dst + 16384u + ldOff[i], Bt + eb);
            }
            cp_commit();
        };

        load_stage(0);
        load_stage(1);

        for (int cidx = 0; cidx < nc; cidx++) {
            if (cidx + 1 < nc) cp_wait1(); else cp_wait0();
            __syncthreads();
            if (cidx + 2 < nc) load_stage(cidx + 2);
            const uint32_t st = sb + (uint32_t)(cidx % 3) * TG_STAGE;
            compute_chunk_f16(st, st + 16384u, apre, ax, ac0, bpre, bx, bc0, c);
        }
        __syncthreads();

        float* sf = (float*)smem;
#pragma unroll
        for (int i = 0; i < 4; i++) {
            const int r = m0 + i * 16 + (lane >> 2);
#pragma unroll
            for (int j = 0; j < 4; j++) {
                const int cc = n0 + j * 8 + (lane & 3) * 2;
                sf[r * 136 + cc]           = c[i][j][0];
                sf[r * 136 + cc + 1]       = c[i][j][1];
                sf[(r + 8) * 136 + cc]     = c[i][j][2];
                sf[(r + 8) * 136 + cc + 1] = c[i][j][3];
            }
        }
        __syncthreads();
#pragma unroll 4
        for (int e = tid; e < 128 * 128; e += TG_THREADS) {
            const int r = e >> 7, cc = e & 127;
            const int gc = colBase + cc;
            outT[(long long)(rowBase + r) * DD + gc] = sf[r * 136 + cc] + bias[gc];
        }
        __syncthreads();   // sf reused as stage smem next tile
    }
}

// ---------------------------------------------------------------------------
// Merged projection GEMM (z = 0: q' ; 1: vproj(trans)).
// ---------------------------------------------------------------------------
struct ProjArgs {
    const float*  A[2];
    const __half* Bh[2];
    __half*       out[2];
    const float*  bias[2];
    int           trans[2];
};

__global__ __launch_bounds__(TG_THREADS, 2)
void tgemm_proj_kernel(ProjArgs pa, int M, int N, int K)
{
    extern __shared__ char smem[];
    const uint32_t sb = smem_u32(smem);
    const int tid  = threadIdx.x;
    const int lane = tid & 31;
    const int wid  = tid >> 5;
    const int m0   = (wid & 1) * 64;
    const int n0   = (wid >> 1) * 32;
    const int z    = blockIdx.z;

    const float* A    = pa.A[z];
    const __half* Bh  = pa.Bh[z];
    __half* out       = pa.out[z];
    const float* bias = pa.bias[z];
    const int transOut = pa.trans[z];

    const int rowBase = blockIdx.y * 128;
    const int colBase = blockIdx.x * 128;

    int ldRow[4], ldCh[4];
    uint32_t ldOff[4];
#pragma unroll
    for (int i = 0; i < 4; i++) {
        const int u = tid + i * 256;
        ldRow[i] = u >> 3;
        ldCh[i]  = u & 7;
        ldOff[i] = tile_off(ldRow[i], ldCh[i]);
    }

    uint32_t apre[4], ax[4], bpre[2], bx[2];
    int ac0, bc0;
    make_off2(lane, m0, n0, apre, ax, ac0, bpre, bx, bc0);

    float c[4][4][4];
#pragma unroll
    for (int i = 0; i < 4; i++)
#pragma unroll
        for (int j = 0; j < 4; j++)
#pragma unroll
            for (int e = 0; e < 4; e++) c[i][j][e] = 0.0f;

    const int nc = K >> 6;

    auto issueB = [&](int cidx) {
        const uint32_t dst = sb + 16384u + (uint32_t)(cidx % 3) * TG_STAGE;
        const long long kb = (long long)cidx * 64;
#pragma unroll
        for (int i = 0; i < 4; i++) {
            const long long eb = (long long)(colBase + ldRow[i]) * K + kb + ldCh[i] * 8;
            cp_async16(dst + ldOff[i], Bh + eb);
        }
        cp_commit();
    };
    auto ldgA = [&](int cidx, float4 ar[4][2]) {
        const long long kb = (long long)cidx * 64;
#pragma unroll
        for (int i = 0; i < 4; i++) {
            const float* p = A + (long long)(rowBase + ldRow[i]) * K + kb + ldCh[i] * 8;
            ar[i][0] = *(const float4*)(p);
            ar[i][1] = *(const float4*)(p + 4);
        }
    };
    auto stsA = [&](int cidx, const float4 ar[4][2]) {
        char* base = smem + (cidx % 3) * TG_STAGE;
#pragma unroll
        for (int i = 0; i < 4; i++) {
            uint4 t;
            __half2 h0 = __floats2half2_rn(ar[i][0].x, ar[i][0].y);
            __half2 h1 = __floats2half2_rn(ar[i][0].z, ar[i][0].w);
            __half2 h2 = __floats2half2_rn(ar[i][1].x, ar[i][1].y);
            __half2 h3 = __floats2half2_rn(ar[i][1].z, ar[i][1].w);
            t.x = *reinterpret_cast<uint32_t*>(&h0);
            t.y = *reinterpret_cast<uint32_t*>(&h1);
            t.z = *reinterpret_cast<uint32_t*>(&h2);
            t.w = *reinterpret_cast<uint32_t*>(&h3);
            *(uint4*)(base + ldOff[i]) = t;
        }
    };

    float4 ar[4][2];
    ldgA(0, ar);
    issueB(0);
    if (nc > 1) issueB(1);
    stsA(0, ar);
    if (nc > 1) ldgA(1, ar);

    for (int cidx = 0; cidx < nc; cidx++) {
        if (cidx + 1 < nc) cp_wait1(); else cp_wait0();
        __syncthreads();
        if (cidx + 2 < nc) issueB(cidx + 2);
        if (cidx + 1 < nc) stsA(cidx + 1, ar);
        if (cidx + 2 < nc) ldgA(cidx + 2, ar);
        const uint32_t st = sb + (uint32_t)(cidx % 3) * TG_STAGE;
        compute_chunk_f16(st, st + 16384u, apre, ax, ac0, bpre, bx, bc0, c);
    }
    __syncthreads();

    float* sf = (float*)smem;
#pragma unroll
    for (int i = 0; i < 4; i++) {
        const int r = m0 + i * 16 + (lane >> 2);
#pragma unroll
        for (int j = 0; j < 4; j++) {
            const int cc = n0 + j * 8 + (lane & 3) * 2;
            sf[r * 136 + cc]           = c[i][j][0];
            sf[r * 136 + cc + 1]       = c[i][j][1];
            sf[(r + 8) * 136 + cc]     = c[i][j][2];
            sf[(r + 8) * 136 + cc + 1] = c[i][j][3];
        }
    }
    __syncthreads();
#pragma unroll 4
    for (int e = tid; e < 128 * 128; e += TG_THREADS) {
        int r, cc;
        if (transOut) { r = e & 127; cc = e >> 7; }
        else          { r = e >> 7;  cc = e & 127; }
        float v = sf[r * 136 + cc] + bias[colBase + cc];
        long long gi;
        if (transOut) {
            const int grow = rowBase + r;
            gi = (long long)(grow >> 11) * ((long long)DD * SS)
               + (long long)(colBase + cc) * SS + (grow & 2047);
        } else {
            gi = (long long)(rowBase + r) * N + colBase + cc;
        }
        out[gi] = __float2half_rn(v);
    }
}

// ---------------------------------------------------------------------------
// Fold GEMM (512^3, fp32): 64x64 tile, BK=16. grid (8,8,2). tn: C = A^T @ B.
// ---------------------------------------------------------------------------
struct FoldArgs {
    const float* A[2];
    const float* B[2];
    float*       C[2];
    int          tn[2];
};

__global__ __launch_bounds__(256)
void fold_gemm_kernel(FoldArgs fa)
{
    const int z = blockIdx.z;
    const float* A = fa.A[z];
    const float* B = fa.B[z];
    float* C = fa.C[z];
    const int tn = fa.tn[z];

    __shared__ float As[16][68];
    __shared__ float Bs[16][68];
    const int tid = threadIdx.x;
    const int tx = tid & 15, ty = tid >> 4;
    const int m0 = blockIdx.y * 64, n0 = blockIdx.x * 64;

    float acc[4][4];
#pragma unroll
    for (int i = 0; i < 4; i++)
#pragma unroll
        for (int j = 0; j < 4; j++) acc[i][j] = 0.0f;

    for (int k0 = 0; k0 < DD; k0 += 16) {
        if (tn) {
            const int kr = tid >> 4, mc = (tid & 15) * 4;
            float4 a = *(const float4*)(A + (long long)(k0 + kr) * DD + m0 + mc);
            *(float4*)&As[kr][mc] = a;
        } else {
            const int r = tid >> 2, kc = (tid & 3) * 4;
            float4 a = *(const float4*)(A + (long long)(m0 + r) * DD + k0 + kc);
            As[kc + 0][r] = a.x; As[kc + 1][r] = a.y;
            As[kc + 2][r] = a.z; As[kc + 3][r] = a.w;
        }
        {
            const int kr = tid >> 4, ncc = (tid & 15) * 4;
            float4 b = *(const float4*)(B + (long long)(k0 + kr) * DD + n0 + ncc);
            *(float4*)&Bs[kr][ncc] = b;
        }
        __syncthreads();
#pragma unroll
        for (int k = 0; k < 16; k++) {
            float4 a = *(const float4*)&As[k][ty * 4];
            float4 b = *(const float4*)&Bs[k][tx * 4];
            float av[4] = {a.x, a.y, a.z, a.w};
            float bv[4] = {b.x, b.y, b.z, b.w};
#pragma unroll
            for (int i = 0; i < 4; i++)
#pragma unroll
                for (int j = 0; j < 4; j++)
                    acc[i][j] = fmaf(av[i], bv[j], acc[i][j]);
        }
        __syncthreads();
    }
#pragma unroll
    for (int i = 0; i < 4; i++) {
        float4 v = {acc[i][0], acc[i][1], acc[i][2], acc[i][3]};
        *(float4*)(C + (long long)(m0 + ty * 4 + i) * DD + n0 + tx * 4) = v;
    }
}

// out[p] = sum_d E'[p,d]*b[d] + (add ? add[p] : 0); transE: E'[p,d] = E[d,p]
__global__ void fuse_bias_kernel(const float* __restrict__ E,
                                 const float* __restrict__ b,
                                 const float* __restrict__ add,
                                 float* __restrict__ out, int transE)
{
    __shared__ float red[8];
    const int p = blockIdx.x;
    float s = 0.0f;
    for (int d = threadIdx.x; d < DD; d += 256) {
        float e = transE ? E[(long long)d * DD + p] : E[(long long)p * DD + d];
        s = fmaf(e, b[d], s);
    }
#pragma unroll
    for (int off = 16; off > 0; off >>= 1) s += __shfl_xor_sync(0xffffffffu, s, off);
    if ((threadIdx.x & 31) == 0) red[threadIdx.x >> 5] = s;
    __syncthreads();
    if (threadIdx.x == 0) {
        float t = 0.0f;
#pragma unroll
        for (int i = 0; i < 8; i++) t += red[i];
        out[p] = t + (add ? add[p] : 0.0f);
    }
}

// convert 2 weight matrices fp32 -> fp16
__global__ void cvt2_kernel(const float* __restrict__ s0, __half* __restrict__ d0,
                            const float* __restrict__ s1, __half* __restrict__ d1)
{
    const float* x = blockIdx.z ? s1 : s0;
    __half* y      = blockIdx.z ? d1 : d0;
    const int n = DD * DD;
    for (int i = blockIdx.x * blockDim.x + threadIdx.x; i < n;
         i += gridDim.x * blockDim.x)
        y[i] = __float2half_rn(x[i]);
}

// big fp32 -> fp16 convert (k_in)
__global__ void cvt_big_kernel(const float* __restrict__ x, __half* __restrict__ y,
                               long long n)
{
    long long i = (long long)blockIdx.x * blockDim.x + threadIdx.x;
    const long long stride = (long long)gridDim.x * blockDim.x;
    for (; i < n; i += stride) {
        float2 v = *(const float2*)(x + i * 2);
        __half2 h = __floats2half2_rn(v.x, v.y);
        *(__half2*)(y + i * 2) = h;
    }
}

// softmax rows of 2048 in place (exact fp32) + fp16 copy — vectorized
__global__ __launch_bounds__(256)
void softmax2048_kernel(float* __restrict__ data, __half* __restrict__ half_out)
{
    const size_t base = (size_t)blockIdx.x * 2048;
    float4* row4 = (float4*)(data + base);
    __half2* h2  = (__half2*)(half_out + base);
    const int tid = threadIdx.x;
    __shared__ float red[8];

    float4 v0 = row4[tid * 2];
    float4 v1 = row4[tid * 2 + 1];
    float v[8] = {v0.x, v0.y, v0.z, v0.w, v1.x, v1.y, v1.z, v1.w};

    float m = -3.4e38f;
#pragma unroll
    for (int i = 0; i < 8; i++) m = fmaxf(m, v[i]);
#pragma unroll
    for (int o = 16; o > 0; o >>= 1) m = fmaxf(m, __shfl_xor_sync(0xffffffffu, m, o));
    if ((tid & 31) == 0) red[tid >> 5] = m;
    __syncthreads();
    float bm = red[0];
#pragma unroll
    for (int i = 1; i < 8; i++) bm = fmaxf(bm, red[i]);
    __syncthreads();

    float s = 0.0f;
#pragma unroll
    for (int i = 0; i < 8; i++) { v[i] = __expf(v[i] - bm); s += v[i]; }
#pragma unroll
    for (int o = 16; o > 0; o >>= 1) s += __shfl_xor_sync(0xffffffffu, s, o);
    if ((tid & 31) == 0) red[tid >> 5] = s;
    __syncthreads();
    float bs = 0.0f;
#pragma unroll
    for (int i = 0; i < 8; i++) bs += red[i];

    const float inv = 1.0f / bs;
#pragma unroll
    for (int i = 0; i < 8; i++) v[i] *= inv;

    row4[tid * 2]     = make_float4(v[0], v[1], v[2], v[3]);
    row4[tid * 2 + 1] = make_float4(v[4], v[5], v[6], v[7]);
#pragma unroll
    for (int i = 0; i < 4; i++)
        h2[tid * 4 + i] = __floats2half2_rn(v[2 * i], v[2 * i + 1]);
}

// ---------------------------------------------------------------------------
// Launch
// ---------------------------------------------------------------------------
extern "C" void kernel_launch(void* const* d_in, const int* in_sizes, int n_in,
                              void* d_out, int out_size)
{
    const float* q_in = (const float*)d_in[0];
    const float* k_in = (const float*)d_in[1];
    const float* v_in = (const float*)d_in[2];
    const float* Wq   = (const float*)d_in[3];
    const float* bq   = (const float*)d_in[4];
    const float* Wk   = (const float*)d_in[5];
    const float* bk   = (const float*)d_in[6];   // softmax-invariant: dropped
    const float* Wv   = (const float*)d_in[7];
    const float* bv   = (const float*)d_in[8];
    const float* E1   = (const float*)d_in[9];
    const float* E2   = (const float*)d_in[10];
    const float* Wo   = (const float*)d_in[11];
    const float* bo   = (const float*)d_in[12];
    (void)bk;

    float* outp = (float*)d_out;
    float* attn = outp + (size_t)BB * SS * DD;

    float *p_Wkp, *p_Bqk, *p_Wvp, *p_Wvo, *p_bqk, *p_bvp, *p_bvo, *p_zero;
    __half *bqk_h, *wvo_h, *p_qp, *p_kin, *p_vpT, *p_ath;
    cudaGetSymbolAddress((void**)&p_Wkp,  g_Wkp);
    cudaGetSymbolAddress((void**)&p_Bqk,  g_Bqk);
    cudaGetSymbolAddress((void**)&p_Wvp,  g_Wvp);
    cudaGetSymbolAddress((void**)&p_Wvo,  g_Wvo);
    cudaGetSymbolAddress((void**)&p_bqk,  g_bqk);
    cudaGetSymbolAddress((void**)&p_bvp,  g_bvp);
    cudaGetSymbolAddress((void**)&p_bvo,  g_bvo);
    cudaGetSymbolAddress((void**)&p_zero, g_zero512);
    cudaGetSymbolAddress((void**)&bqk_h,  g_Bqk_h);
    cudaGetSymbolAddress((void**)&wvo_h,  g_Wvo_h);
    cudaGetSymbolAddress((void**)&p_qp,   g_qp_h);
    cudaGetSymbolAddress((void**)&p_kin,  g_kin_h);
    cudaGetSymbolAddress((void**)&p_vpT,  g_vpT_h);
    cudaGetSymbolAddress((void**)&p_ath,  g_attn_h);

    cudaFuncSetAttribute(tgemm_f16_kernel, cudaFuncAttributeMaxDynamicSharedMemorySize, TG_SMEM);
    cudaFuncSetAttribute(tgemm_av_persist_kernel, cudaFuncAttributeMaxDynamicSharedMemorySize, TG_SMEM);
    cudaFuncSetAttribute(tgemm_proj_kernel, cudaFuncAttributeMaxDynamicSharedMemorySize, TG_SMEM);

    const int M = BB * SS;
    const float scaling = 1.0f / sqrtf((float)DD);

    // --- fold chain ---
    cvt_big_kernel<<<2048, 256>>>(k_in, p_kin, (long long)BB * SS * DD / 2);
    {
        FoldArgs f1;
        f1.A[0] = E1; f1.B[0] = Wk; f1.C[0] = p_Wkp; f1.tn[0] = 0;
        f1.A[1] = E2; f1.B[1] = Wv; f1.C[1] = p_Wvp; f1.tn[1] = 0;
        fold_gemm_kernel<<<dim3(8, 8, 2), 256>>>(f1);
    }
    {
        FoldArgs f2;
        f2.A[0] = p_Wkp; f2.B[0] = Wq;    f2.C[0] = p_Bqk; f2.tn[0] = 1;
        f2.A[1] = Wo;    f2.B[1] = p_Wvp; f2.C[1] = p_Wvo; f2.tn[1] = 0;
        fold_gemm_kernel<<<dim3(8, 8, 2), 256>>>(f2);
    }
    fuse_bias_kernel<<<DD, 256>>>(p_Wkp, bq, nullptr, p_bqk, 1);
    fuse_bias_kernel<<<DD, 256>>>(E2, bv, nullptr, p_bvp, 0);
    fuse_bias_kernel<<<DD, 256>>>(Wo, p_bvp, bo, p_bvo, 0);
    cvt2_kernel<<<dim3(128, 1, 2), 256>>>(p_Bqk, bqk_h, p_Wvo, wvo_h);

    // --- projections: q' = qin@Bqk^T + bqk ; vprojT = (v_in@Wvo^T)^T ---
    {
        ProjArgs pa;
        pa.A[0] = q_in; pa.Bh[0] = bqk_h; pa.out[0] = p_qp;  pa.bias[0] = p_bqk;  pa.trans[0] = 0;
        pa.A[1] = v_in; pa.Bh[1] = wvo_h; pa.out[1] = p_vpT; pa.bias[1] = p_zero; pa.trans[1] = 1;
        tgemm_proj_kernel<<<dim3(DD / 128, M / 128, 2), TG_THREADS, TG_SMEM>>>(pa, M, DD, DD);
    }

    // --- scores = scaling * q' @ kin^T -> attn region fp32 ---
    tgemm_f16_kernel<<<dim3(SS / 128, SS / 128, BB), TG_THREADS, TG_SMEM>>>(
        p_qp, p_kin, attn, nullptr, nullptr, SS, SS, DD, scaling,
        (long long)SS * DD, (long long)SS * DD, (long long)SS * SS);

    // --- softmax in place + fp16 copy ---
    softmax2048_kernel<<<BB * SS, 256>>>(attn, p_ath);

    // --- out = attn @ vpT^T + bvo  (persistent: 296 CTAs over 1024 tiles) ---
    tgemm_av_persist_kernel<<<296, TG_THREADS, TG_SMEM>>>(p_ath, p_vpT, outp, p_bvo);
}